// round 2
// baseline (speedup 1.0000x reference)
#include <cuda_runtime.h>
#include <cuda_bf16.h>
#include <math.h>

#define NB 32768
#define ND 128
#define NH 512
#define NE 16
#define HCHUNK 128
#define NCHUNKS (NH / HCHUNK)

#define XS_STRIDE 132   // A-operand tiles (X, H): bank-conflict-free A frags
#define WS_STRIDE 136   // B-operand tiles (W1c, W2c): bank-conflict-free B frags

// Scratch (no runtime allocation allowed)
__device__ int g_counts[NE];
__device__ int g_bucket[NE * NB];

__global__ void zero_counts_kernel() {
    if (threadIdx.x < NE) g_counts[threadIdx.x] = 0;
}

// ---------------------------------------------------------------------------
// Routing: per-thread token gating. logits = x[b]·wg + bg ; argmax (lowest
// index on ties, matching jax.lax.top_k). softmax over k=1 is exactly 1.0,
// so only the index matters.
// ---------------------------------------------------------------------------
__global__ void route_kernel(const float* __restrict__ x,
                             const float* __restrict__ wg,
                             const float* __restrict__ bg) {
    __shared__ float swg[ND * NE];
    __shared__ float sbg[NE];
    for (int i = threadIdx.x; i < ND * NE; i += blockDim.x) swg[i] = wg[i];
    if (threadIdx.x < NE) sbg[threadIdx.x] = bg[threadIdx.x];
    __syncthreads();

    int b = blockIdx.x * blockDim.x + threadIdx.x;
    if (b >= NB) return;
    const float* xr = x + (size_t)b * ND;

    float acc[NE];
#pragma unroll
    for (int e = 0; e < NE; e++) acc[e] = sbg[e];
#pragma unroll 4
    for (int d = 0; d < ND; d++) {
        float xv = __ldg(xr + d);
#pragma unroll
        for (int e = 0; e < NE; e++) acc[e] = fmaf(xv, swg[d * NE + e], acc[e]);
    }
    float best = acc[0]; int bi = 0;
#pragma unroll
    for (int e = 1; e < NE; e++) {
        if (acc[e] > best) { best = acc[e]; bi = e; }
    }
    int pos = atomicAdd(&g_counts[bi], 1);
    g_bucket[bi * NB + pos] = b;
}

// ---------------------------------------------------------------------------
// Expert GEMM: one block = (expert e, 128-token tile). Fused two-GEMM over
// 4 h-chunks: O += gelu(X @ W1[:,hc]) @ W2[hc,:]. tf32 mma.sync, fp32 accum.
// ---------------------------------------------------------------------------
__device__ __forceinline__ unsigned f2tf32(float f) {
    unsigned r;
    asm("cvt.rna.tf32.f32 %0, %1;" : "=r"(r) : "f"(f));
    return r;
}

__device__ __forceinline__ float gelu_exact(float v) {
    return 0.5f * v * (1.0f + erff(v * 0.70710678118654752440f));
}

__device__ __forceinline__ void mma_tf32(float c[4], const unsigned a[4], const unsigned b[2]) {
    asm volatile(
        "mma.sync.aligned.m16n8k8.row.col.f32.tf32.tf32.f32 "
        "{%0,%1,%2,%3}, {%4,%5,%6,%7}, {%8,%9}, {%0,%1,%2,%3};\n"
        : "+f"(c[0]), "+f"(c[1]), "+f"(c[2]), "+f"(c[3])
        : "r"(a[0]), "r"(a[1]), "r"(a[2]), "r"(a[3]), "r"(b[0]), "r"(b[1]));
}

// 128x128x128 tile GEMM: C[2][8][4] += A(XS_STRIDE) @ B(WS_STRIDE).
// 8 warps in 4(m) x 2(n): warp tile 32x64, micro m16n8k8.
__device__ __forceinline__ void gemm_tile(const float* __restrict__ A,
                                          const float* __restrict__ Bm,
                                          float C[2][8][4],
                                          int rowBase, int colBase, int lane) {
    int gid = lane >> 2;   // 0..7
    int tig = lane & 3;    // 0..3
#pragma unroll
    for (int ks = 0; ks < 16; ks++) {
        int kk = ks * 8;
        unsigned a[2][4];
#pragma unroll
        for (int mt = 0; mt < 2; mt++) {
            const float* ap = A + (rowBase + mt * 16 + gid) * XS_STRIDE + kk + tig;
            a[mt][0] = __float_as_uint(ap[0]);
            a[mt][1] = __float_as_uint(ap[8 * XS_STRIDE]);
            a[mt][2] = __float_as_uint(ap[4]);
            a[mt][3] = __float_as_uint(ap[8 * XS_STRIDE + 4]);
        }
        unsigned bf[8][2];
#pragma unroll
        for (int nt = 0; nt < 8; nt++) {
            const float* bp = Bm + (kk + tig) * WS_STRIDE + colBase + nt * 8 + gid;
            bf[nt][0] = __float_as_uint(bp[0]);
            bf[nt][1] = __float_as_uint(bp[4 * WS_STRIDE]);
        }
#pragma unroll
        for (int mt = 0; mt < 2; mt++)
#pragma unroll
            for (int nt = 0; nt < 8; nt++)
                mma_tf32(C[mt][nt], a[mt], bf[nt]);
    }
}

__global__ __launch_bounds__(256, 1)
void expert_gemm_kernel(const float* __restrict__ x,
                        const float* __restrict__ w1,
                        const float* __restrict__ w2,
                        float* __restrict__ out) {
    extern __shared__ float smem[];
    float* Xs = smem;                         // [128][XS_STRIDE]  tf32
    float* Ws = Xs + 128 * XS_STRIDE;         // [128][WS_STRIDE]  tf32 (W1c then W2c)
    float* Hs = Ws + 128 * WS_STRIDE;         // [128][XS_STRIDE]  tf32 (gelu hidden)
    int*   stok = (int*)(Hs + 128 * XS_STRIDE); // [128] token ids

    const int e = blockIdx.y;
    const int count = g_counts[e];
    const int base = blockIdx.x * 128;
    if (base >= count) return;

    const int tid = threadIdx.x;
    const int lane = tid & 31;
    const int warp = tid >> 5;
    const int rowBase = (warp & 3) * 32;
    const int colBase = (warp >> 2) * 64;
    const int gid = lane >> 2;
    const int tig = lane & 3;

    // ---- load X tile (gathered token rows), 2 threads per row ----
    {
        int row = tid >> 1;
        int half = (tid & 1) * 64;
        int gi = base + row;
        int tok = (gi < count) ? g_bucket[e * NB + gi] : -1;
        if ((tid & 1) == 0) stok[row] = tok;
        float* dst = Xs + row * XS_STRIDE + half;
        if (tok >= 0) {
            const float4* src = (const float4*)(x + (size_t)tok * ND + half);
#pragma unroll
            for (int j = 0; j < 16; j++) {
                float4 v = src[j];
                dst[j * 4 + 0] = __uint_as_float(f2tf32(v.x));
                dst[j * 4 + 1] = __uint_as_float(f2tf32(v.y));
                dst[j * 4 + 2] = __uint_as_float(f2tf32(v.z));
                dst[j * 4 + 3] = __uint_as_float(f2tf32(v.w));
            }
        } else {
#pragma unroll
            for (int j = 0; j < 64; j++) dst[j] = 0.0f;
        }
    }

    float c2[2][8][4];
#pragma unroll
    for (int mt = 0; mt < 2; mt++)
#pragma unroll
        for (int nt = 0; nt < 8; nt++)
#pragma unroll
            for (int q = 0; q < 4; q++) c2[mt][nt][q] = 0.0f;

    for (int hc = 0; hc < NCHUNKS; hc++) {
        // protects Ws/Hs from prior chunk readers; also orders Xs load (hc=0)
        __syncthreads();

        // ---- load W1 chunk: Ws[k=d][n=h] (coalesced: h contiguous in gmem) ----
        {
            int row = tid >> 1;            // d
            int half = (tid & 1) * 64;
            const float4* src = (const float4*)(w1 + ((size_t)(e * ND + row)) * NH + hc * HCHUNK + half);
            float* dst = Ws + row * WS_STRIDE + half;
#pragma unroll
            for (int j = 0; j < 16; j++) {
                float4 v = src[j];
                dst[j * 4 + 0] = __uint_as_float(f2tf32(v.x));
                dst[j * 4 + 1] = __uint_as_float(f2tf32(v.y));
                dst[j * 4 + 2] = __uint_as_float(f2tf32(v.z));
                dst[j * 4 + 3] = __uint_as_float(f2tf32(v.w));
            }
        }
        __syncthreads();

        // ---- GEMM1: C1 = X @ W1c ----
        float c1[2][8][4];
#pragma unroll
        for (int mt = 0; mt < 2; mt++)
#pragma unroll
            for (int nt = 0; nt < 8; nt++)
#pragma unroll
                for (int q = 0; q < 4; q++) c1[mt][nt][q] = 0.0f;

        gemm_tile(Xs, Ws, c1, rowBase, colBase, lane);

        // ---- gelu -> Hs (tf32) ----
#pragma unroll
        for (int mt = 0; mt < 2; mt++) {
            int r0 = rowBase + mt * 16 + gid;
#pragma unroll
            for (int nt = 0; nt < 8; nt++) {
                int col = colBase + nt * 8 + tig * 2;
                Hs[r0 * XS_STRIDE + col]           = __uint_as_float(f2tf32(gelu_exact(c1[mt][nt][0])));
                Hs[r0 * XS_STRIDE + col + 1]       = __uint_as_float(f2tf32(gelu_exact(c1[mt][nt][1])));
                Hs[(r0 + 8) * XS_STRIDE + col]     = __uint_as_float(f2tf32(gelu_exact(c1[mt][nt][2])));
                Hs[(r0 + 8) * XS_STRIDE + col + 1] = __uint_as_float(f2tf32(gelu_exact(c1[mt][nt][3])));
            }
        }
        __syncthreads();   // all GEMM1 Ws-reads + Hs writes done

        // ---- load W2 chunk: Ws[k=h][n=d] (coalesced: d contiguous in gmem) ----
        {
            int row = tid >> 1;            // h within chunk
            int half = (tid & 1) * 64;
            const float4* src = (const float4*)(w2 + ((size_t)(e * NH + hc * HCHUNK + row)) * ND + half);
            float* dst = Ws + row * WS_STRIDE + half;
#pragma unroll
            for (int j = 0; j < 16; j++) {
                float4 v = src[j];
                dst[j * 4 + 0] = __uint_as_float(f2tf32(v.x));
                dst[j * 4 + 1] = __uint_as_float(f2tf32(v.y));
                dst[j * 4 + 2] = __uint_as_float(f2tf32(v.z));
                dst[j * 4 + 3] = __uint_as_float(f2tf32(v.w));
            }
        }
        __syncthreads();

        // ---- GEMM2: C2 += gelu(H) @ W2c ----
        gemm_tile(Hs, Ws, c2, rowBase, colBase, lane);
    }

    // ---- epilogue: scatter O rows to out[token] (score == 1.0 exactly) ----
#pragma unroll
    for (int mt = 0; mt < 2; mt++) {
        int r0 = rowBase + mt * 16 + gid;
#pragma unroll
        for (int half = 0; half < 2; half++) {
            int r = r0 + half * 8;
            int tok = stok[r];
            if (tok >= 0) {
                float* o = out + (size_t)tok * ND;
#pragma unroll
                for (int nt = 0; nt < 8; nt++) {
                    int col = colBase + nt * 8 + tig * 2;
                    o[col]     = c2[mt][nt][2 * half];
                    o[col + 1] = c2[mt][nt][2 * half + 1];
                }
            }
        }
    }
}

// ---------------------------------------------------------------------------

extern "C" void kernel_launch(void* const* d_in, const int* in_sizes, int n_in,
                              void* d_out, int out_size) {
    const float* x  = (const float*)d_in[0];
    const float* w1 = (const float*)d_in[1];
    const float* w2 = (const float*)d_in[2];
    const float* wg = (const float*)d_in[3];
    const float* bg = (const float*)d_in[4];
    float* out = (float*)d_out;

    zero_counts_kernel<<<1, 32>>>();
    route_kernel<<<NB / 256, 256>>>(x, wg, bg);

    int smem_bytes = (128 * XS_STRIDE * 2 + 128 * WS_STRIDE) * (int)sizeof(float)
                     + 128 * (int)sizeof(int);
    cudaFuncSetAttribute(expert_gemm_kernel,
                         cudaFuncAttributeMaxDynamicSharedMemorySize, smem_bytes);
    expert_gemm_kernel<<<dim3(256, NE), 256, smem_bytes>>>(x, w1, w2, out);
}

// round 6
// speedup vs baseline: 1.4034x; 1.4034x over previous
#include <cuda_runtime.h>
#include <math.h>
#include <cstdint>

#define NB 32768
#define ND 128
#define NH 512
#define NE 16
#define CHUNK 64
#define NCHUNKS (NH / CHUNK)
#define NSTAGES (NCHUNKS * 2)   // 16: G1/G2 alternating
#define TILES_PER_E 20          // grid width; grid-stride loop handles overflow

// strides in words (floats), chosen for conflict-free frag access
#define XS 132   // X  tile [128][128] A-operand   (S%32==4)
#define HS 68    // H  tile [128][64]  A-operand   (S%32==4)
#define WS1 72   // W1 tile [k=128][n=64] B-operand (S%32==8)
#define WS2 136  // W2 tile [k=64][n=128] B-operand (S%32==8)

#define SLOT_WORDS 9216          // max(128*72, 64*136)
#define OFF_X 0
#define OFF_H (128 * XS)                   // 16896
#define OFF_W (OFF_H + 128 * HS)           // 25600
#define SMEM_WORDS (OFF_W + 3 * SLOT_WORDS + 128)  // + stok
#define SMEM_BYTES (SMEM_WORDS * 4)

// ---------------- scratch ----------------
__device__ int g_counts[NE];
__device__ int g_bucket[NE * NB];

// ---------------- helpers ----------------
__device__ __forceinline__ uint32_t smem_u32(const void* p) {
    uint32_t a;
    asm("{ .reg .u64 t; cvta.to.shared.u64 t, %1; cvt.u32.u64 %0, t; }" : "=r"(a) : "l"(p));
    return a;
}
__device__ __forceinline__ void cp16(uint32_t dst, const void* src) {
    asm volatile("cp.async.ca.shared.global [%0], [%1], 16;" :: "r"(dst), "l"(src));
}
#define CP_COMMIT() asm volatile("cp.async.commit_group;" ::: "memory")
#define CP_WAIT2()  asm volatile("cp.async.wait_group 2;" ::: "memory")

__device__ __forceinline__ uint32_t f2tf32(float f) {
    uint32_t r;
    asm("cvt.rna.tf32.f32 %0, %1;" : "=r"(r) : "f"(f));
    return r;
}
__device__ __forceinline__ uint32_t u2tf32(uint32_t u) {
    uint32_t r;
    asm("cvt.rna.tf32.f32 %0, %1;" : "=r"(r) : "f"(__uint_as_float(u)));
    return r;
}
__device__ __forceinline__ float gelu_exact(float v) {
    return 0.5f * v * (1.0f + erff(v * 0.70710678118654752440f));
}
__device__ __forceinline__ void mma_tf32(float c[4], const uint32_t a[4], const uint32_t b[2]) {
    asm volatile(
        "mma.sync.aligned.m16n8k8.row.col.f32.tf32.tf32.f32 "
        "{%0,%1,%2,%3}, {%4,%5,%6,%7}, {%8,%9}, {%0,%1,%2,%3};\n"
        : "+f"(c[0]), "+f"(c[1]), "+f"(c[2]), "+f"(c[3])
        : "r"(a[0]), "r"(a[1]), "r"(a[2]), "r"(a[3]), "r"(b[0]), "r"(b[1]));
}

// Warp tile GEMM: 2 mtiles (m16) x NT ntiles (n8) x KS kslices (k8).
// A is pre-converted tf32 in smem; B is raw fp32 staged by cp.async, so
// B-frags get cvt.rna.tf32 after the LDS (avoids RZ-truncation bias).
template <int KS, int NT, int AS, int BS>
__device__ __forceinline__ void gemm_warp(const float* __restrict__ A,
                                          const float* __restrict__ B,
                                          float C[2][NT > 4 ? 8 : 4][4],
                                          int mrow, int nbase, int gid, int tig) {
#pragma unroll
    for (int ks = 0; ks < KS; ks++) {
        const int kk = ks * 8;
        uint32_t a[2][4];
#pragma unroll
        for (int mt = 0; mt < 2; mt++) {
            const float* ap = A + (mrow + mt * 16 + gid) * AS + kk + tig;
            a[mt][0] = __float_as_uint(ap[0]);
            a[mt][1] = __float_as_uint(ap[8 * AS]);
            a[mt][2] = __float_as_uint(ap[4]);
            a[mt][3] = __float_as_uint(ap[8 * AS + 4]);
        }
        uint32_t bf[NT][2];
#pragma unroll
        for (int nt = 0; nt < NT; nt++) {
            const float* bp = B + (kk + tig) * BS + nbase + nt * 8 + gid;
            bf[nt][0] = u2tf32(__float_as_uint(bp[0]));
            bf[nt][1] = u2tf32(__float_as_uint(bp[4 * BS]));
        }
#pragma unroll
        for (int mt = 0; mt < 2; mt++)
#pragma unroll
            for (int nt = 0; nt < NT; nt++)
                mma_tf32(C[mt][nt], a[mt], bf[nt]);
    }
}

// ---------------------------------------------------------------------------
__global__ void zero_counts_kernel() {
    if (threadIdx.x < NE) g_counts[threadIdx.x] = 0;
}

__global__ void route_kernel(const float* __restrict__ x,
                             const float* __restrict__ wg,
                             const float* __restrict__ bg) {
    __shared__ float swg[ND * NE];
    __shared__ float sbg[NE];
    for (int i = threadIdx.x; i < ND * NE; i += blockDim.x) swg[i] = wg[i];
    if (threadIdx.x < NE) sbg[threadIdx.x] = bg[threadIdx.x];
    __syncthreads();

    int b = blockIdx.x * blockDim.x + threadIdx.x;
    if (b >= NB) return;
    const float* xr = x + (size_t)b * ND;

    float acc[NE];
#pragma unroll
    for (int e = 0; e < NE; e++) acc[e] = sbg[e];
#pragma unroll 4
    for (int d = 0; d < ND; d++) {
        float xv = __ldg(xr + d);
#pragma unroll
        for (int e = 0; e < NE; e++) acc[e] = fmaf(xv, swg[d * NE + e], acc[e]);
    }
    float best = acc[0]; int bi = 0;
#pragma unroll
    for (int e = 1; e < NE; e++)
        if (acc[e] > best) { best = acc[e]; bi = e; }
    int pos = atomicAdd(&g_counts[bi], 1);
    g_bucket[bi * NB + pos] = b;
}

// ---------------------------------------------------------------------------
// Expert kernel: block = (expert, tile-slot), grid-stride over 128-token
// tiles (handles arbitrarily skewed expert counts). 256 threads, 8 warps as
// 4(m) x 2(n). cp.async 3-slot ring pipelines W1/W2 chunk loads against MMA.
// ---------------------------------------------------------------------------
__global__ __launch_bounds__(256, 1)
void expert_gemm_pipe(const float* __restrict__ x,
                      const float* __restrict__ w1,
                      const float* __restrict__ w2,
                      float* __restrict__ out) {
    extern __shared__ __align__(128) float smem[];

    const int e = blockIdx.y;
    const int count = g_counts[e];

    const uint32_t sb = smem_u32(smem);
    const int tid = threadIdx.x;
    const int lane = tid & 31;
    const int warp = tid >> 5;
    const int mg = warp & 3;          // m-group: rows [mg*32, +32)
    const int nh = warp >> 2;         // n-half
    const int mrow = mg * 32;
    const int gid = lane >> 2;
    const int tig = lane & 3;
    int* stok = (int*)(smem + OFF_W + 3 * SLOT_WORDS);

    const float* w1e = w1 + (size_t)e * ND * NH;
    const float* w2e = w2 + (size_t)e * NH * ND;

    for (int base = blockIdx.x * 128; base < count; base += TILES_PER_E * 128) {

        // ---- prologue: issue first 3 weight-chunk loads (stages 0,1,2) ----
        {
            uint32_t wbase = sb + (OFF_W + 0 * SLOT_WORDS) * 4;
#pragma unroll
            for (int i = 0; i < 8; i++) {
                int t = tid + i * 256;            // 2048 16B segments
                int d = t >> 4, c4 = (t & 15) * 4;
                cp16(wbase + (d * WS1 + c4) * 4, w1e + (size_t)d * NH + 0 * CHUNK + c4);
            }
            CP_COMMIT();
            wbase = sb + (OFF_W + 1 * SLOT_WORDS) * 4;
#pragma unroll
            for (int i = 0; i < 8; i++) {
                int t = tid + i * 256;
                int h = t >> 5, c4 = (t & 31) * 4;
                cp16(wbase + (h * WS2 + c4) * 4, w2e + (size_t)(0 * CHUNK + h) * ND + c4);
            }
            CP_COMMIT();
            wbase = sb + (OFF_W + 2 * SLOT_WORDS) * 4;
#pragma unroll
            for (int i = 0; i < 8; i++) {
                int t = tid + i * 256;
                int d = t >> 4, c4 = (t & 15) * 4;
                cp16(wbase + (d * WS1 + c4) * 4, w1e + (size_t)d * NH + 1 * CHUNK + c4);
            }
            CP_COMMIT();
        }

        // ---- X tile: gathered token rows -> tf32(RNA) (overlaps cp.async) ----
        {
            int row = tid >> 1;
            int half = (tid & 1) * 64;
            int gi = base + row;
            int tok = (gi < count) ? g_bucket[e * NB + gi] : -1;
            if ((tid & 1) == 0) stok[row] = tok;
            float* dst = smem + OFF_X + row * XS + half;
            if (tok >= 0) {
                const float4* src = (const float4*)(x + (size_t)tok * ND + half);
#pragma unroll
                for (int j = 0; j < 16; j++) {
                    float4 v = src[j];
                    dst[j * 4 + 0] = __uint_as_float(f2tf32(v.x));
                    dst[j * 4 + 1] = __uint_as_float(f2tf32(v.y));
                    dst[j * 4 + 2] = __uint_as_float(f2tf32(v.z));
                    dst[j * 4 + 3] = __uint_as_float(f2tf32(v.w));
                }
            } else {
#pragma unroll
                for (int j = 0; j < 64; j++) dst[j] = 0.0f;
            }
        }
        __syncthreads();   // X + stok visible before first GEMM1

        float c2[2][8][4];
#pragma unroll
        for (int mt = 0; mt < 2; mt++)
#pragma unroll
            for (int nt = 0; nt < 8; nt++)
#pragma unroll
                for (int q = 0; q < 4; q++) c2[mt][nt][q] = 0.0f;

#pragma unroll 1
        for (int s = 0; s < NSTAGES; s++) {
            CP_WAIT2();          // group for stage s complete (<=2 younger pending)
            __syncthreads();

            const float* W = smem + OFF_W + (s % 3) * SLOT_WORDS;

            if ((s & 1) == 0) {
                // ---- GEMM1: c1 = X @ W1c  (M128 x N64 x K128), gelu -> H ----
                float c1[2][4][4];
#pragma unroll
                for (int mt = 0; mt < 2; mt++)
#pragma unroll
                    for (int nt = 0; nt < 4; nt++)
#pragma unroll
                        for (int q = 0; q < 4; q++) c1[mt][nt][q] = 0.0f;

                gemm_warp<16, 4, XS, WS1>(smem + OFF_X, W, c1, mrow, nh * 32, gid, tig);

#pragma unroll
                for (int mt = 0; mt < 2; mt++) {
                    int r0 = mrow + mt * 16 + gid;
#pragma unroll
                    for (int nt = 0; nt < 4; nt++) {
                        int col = nh * 32 + nt * 8 + tig * 2;
                        float* h0 = smem + OFF_H + r0 * HS + col;
                        float* h1 = smem + OFF_H + (r0 + 8) * HS + col;
                        h0[0] = __uint_as_float(f2tf32(gelu_exact(c1[mt][nt][0])));
                        h0[1] = __uint_as_float(f2tf32(gelu_exact(c1[mt][nt][1])));
                        h1[0] = __uint_as_float(f2tf32(gelu_exact(c1[mt][nt][2])));
                        h1[1] = __uint_as_float(f2tf32(gelu_exact(c1[mt][nt][3])));
                    }
                }
            } else {
                // ---- GEMM2: c2 += H @ W2c  (M128 x N128 x K64) ----
                gemm_warp<8, 8, HS, WS2>(smem + OFF_H, W, c2, mrow, nh * 64, gid, tig);
            }
            __syncthreads();     // slot s%3 + H free for reuse

            // ---- issue load for stage s+3 into the slot just freed ----
            int ns = s + 3;
            if (ns < NSTAGES) {
                uint32_t wbase = sb + (OFF_W + (ns % 3) * SLOT_WORDS) * 4;
                int hc = ns >> 1;
                if ((ns & 1) == 0) {
#pragma unroll
                    for (int i = 0; i < 8; i++) {
                        int t = tid + i * 256;
                        int d = t >> 4, c4 = (t & 15) * 4;
                        cp16(wbase + (d * WS1 + c4) * 4, w1e + (size_t)d * NH + hc * CHUNK + c4);
                    }
                } else {
#pragma unroll
                    for (int i = 0; i < 8; i++) {
                        int t = tid + i * 256;
                        int h = t >> 5, c4 = (t & 31) * 4;
                        cp16(wbase + (h * WS2 + c4) * 4, w2e + (size_t)(hc * CHUNK + h) * ND + c4);
                    }
                }
            }
            CP_COMMIT();         // empty groups in the tail keep wait_group 2 exact
        }

        // ---- epilogue: c2 -> out[token] (top-1 softmax score == 1.0) ----
#pragma unroll
        for (int mt = 0; mt < 2; mt++) {
            int r0 = mrow + mt * 16 + gid;
#pragma unroll
            for (int half = 0; half < 2; half++) {
                int r = r0 + half * 8;
                int tok = stok[r];
                if (tok >= 0) {
                    float* o = out + (size_t)tok * ND;
#pragma unroll
                    for (int nt = 0; nt < 8; nt++) {
                        int col = nh * 64 + nt * 8 + tig * 2;
                        float2 v = make_float2(c2[mt][nt][2 * half], c2[mt][nt][2 * half + 1]);
                        *(float2*)(o + col) = v;
                    }
                }
            }
        }
        __syncthreads();   // stok/smem safe to reuse in next tile iteration
    }
}

// ---------------------------------------------------------------------------
extern "C" void kernel_launch(void* const* d_in, const int* in_sizes, int n_in,
                              void* d_out, int out_size) {
    const float* x  = (const float*)d_in[0];
    const float* w1 = (const float*)d_in[1];
    const float* w2 = (const float*)d_in[2];
    const float* wg = (const float*)d_in[3];
    const float* bg = (const float*)d_in[4];
    float* out = (float*)d_out;

    zero_counts_kernel<<<1, 32>>>();
    route_kernel<<<NB / 256, 256>>>(x, wg, bg);

    cudaFuncSetAttribute(expert_gemm_pipe,
                         cudaFuncAttributeMaxDynamicSharedMemorySize, SMEM_BYTES);
    expert_gemm_pipe<<<dim3(TILES_PER_E, NE), 256, SMEM_BYTES>>>(x, w1, w2, out);
}